// round 14
// baseline (speedup 1.0000x reference)
#include <cuda_runtime.h>
#include <cuda_bf16.h>
#include <math.h>
#include <stdint.h>

// Problem constants
#define BSZ   2
#define LSEQ  2048
#define DIM_  2048
#define HEADS 32
#define HD    64
#define QKVD  3072
#define MTOK  4096

#define NSM_CTAS 296   // 148 SMs x 2 CTAs: persistent grid size

// Scratch (device globals; no allocation allowed)
__device__ __nv_bfloat16 g_xb   [(size_t)MTOK * DIM_];
__device__ __nv_bfloat16 g_wqkvb[(size_t)QKVD * DIM_];
__device__ __nv_bfloat16 g_woutb[(size_t)DIM_ * DIM_];
__device__ __nv_bfloat16 g_qkvb [(size_t)MTOK * QKVD];
__device__ __nv_bfloat16 g_aob  [(size_t)MTOK * DIM_];

#define SL2E 0.18033688011112042f   // 0.125 * log2(e), folded into Q at GEMM1

// ---------------------------------------------------------------------------
// Helpers
// ---------------------------------------------------------------------------
__device__ __forceinline__ uint32_t pk_bf2(float lo, float hi) {
    uint32_t r;
    asm("cvt.rn.bf16x2.f32 %0, %1, %2;" : "=r"(r) : "f"(hi), "f"(lo));
    return r;
}

__device__ __forceinline__ void mma_bf16(float c[4], const uint32_t a[4], const uint32_t b[2]) {
    asm volatile(
        "mma.sync.aligned.m16n8k16.row.col.f32.bf16.bf16.f32 "
        "{%0,%1,%2,%3}, {%4,%5,%6,%7}, {%8,%9}, {%0,%1,%2,%3};\n"
        : "+f"(c[0]), "+f"(c[1]), "+f"(c[2]), "+f"(c[3])
        : "r"(a[0]), "r"(a[1]), "r"(a[2]), "r"(a[3]), "r"(b[0]), "r"(b[1]));
}

__device__ __forceinline__ void ldm_x4(uint32_t r[4], uint32_t addr) {
    asm volatile("ldmatrix.sync.aligned.m8n8.x4.shared.b16 {%0,%1,%2,%3}, [%4];\n"
                 : "=r"(r[0]), "=r"(r[1]), "=r"(r[2]), "=r"(r[3]) : "r"(addr));
}
__device__ __forceinline__ void ldm_x4t(uint32_t r[4], uint32_t addr) {
    asm volatile("ldmatrix.sync.aligned.m8n8.x4.trans.shared.b16 {%0,%1,%2,%3}, [%4];\n"
                 : "=r"(r[0]), "=r"(r[1]), "=r"(r[2]), "=r"(r[3]) : "r"(addr));
}

__device__ __forceinline__ void cp16(uint32_t dst, const void* src) {
    asm volatile("cp.async.cg.shared.global [%0], [%1], 16;\n" :: "r"(dst), "l"(src));
}
__device__ __forceinline__ void cp_commit() {
    asm volatile("cp.async.commit_group;\n");
}

// exp2 on the MUFU pipe (parallel to FMA + tensor pipes)
__device__ __forceinline__ float ex2m(float x) {
    float r;
    asm("ex2.approx.f32 %0, %1;" : "=f"(r) : "f"(x));
    return r;
}

// ---------------------------------------------------------------------------
// fused fp32 -> bf16 conversion of x, w_qkv, w_out (one launch)
// ---------------------------------------------------------------------------
#define CVT_N1 (MTOK * DIM_)
#define CVT_N2 (QKVD * DIM_)
#define CVT_N3 (DIM_ * DIM_)
#define CVT_TOTAL (CVT_N1 + CVT_N2 + CVT_N3)

__global__ void __launch_bounds__(256) cvt3_kernel(
    const float* __restrict__ s1, __nv_bfloat16* __restrict__ d1,
    const float* __restrict__ s2, __nv_bfloat16* __restrict__ d2,
    const float* __restrict__ s3, __nv_bfloat16* __restrict__ d3)
{
    int i = (blockIdx.x * 256 + threadIdx.x) * 8;
    const float* s;
    __nv_bfloat16* d;
    if (i < CVT_N1)                  { s = s1 + i;                 d = d1 + i; }
    else if (i < CVT_N1 + CVT_N2)    { s = s2 + (i - CVT_N1);      d = d2 + (i - CVT_N1); }
    else if (i < CVT_TOTAL)          { s = s3 + (i - CVT_N1 - CVT_N2); d = d3 + (i - CVT_N1 - CVT_N2); }
    else return;
    float4 a = *(const float4*)s;
    float4 b = *(const float4*)(s + 4);
    uint4 o;
    o.x = pk_bf2(a.x, a.y);
    o.y = pk_bf2(a.z, a.w);
    o.z = pk_bf2(b.x, b.y);
    o.w = pk_bf2(b.z, b.w);
    *(uint4*)d = o;
}

// ---------------------------------------------------------------------------
// PERSISTENT bf16 NT GEMM: BM=128, BN=128, BK=64, 3-stage cp.async.
// 128 threads = 4 warps of 64x64, 2 CTAs/SM, grid = NSM_CTAS; each CTA loops
// over tiles, eliminating wave-quantization tails.
// ---------------------------------------------------------------------------
#define ASTG 16384
#define GSTG 32768
#define GEMM_SMEM (3 * GSTG)   // 98304

__global__ void __launch_bounds__(128, 2) gemm_bf16_kernel(
    const __nv_bfloat16* __restrict__ A, const __nv_bfloat16* __restrict__ B,
    const float* __restrict__ res, float* __restrict__ Cf,
    __nv_bfloat16* __restrict__ Cb, int M, int N, int K)
{
    extern __shared__ uint8_t dsm[];
    const int tid  = threadIdx.x;
    const int lane = tid & 31;
    const int wid  = tid >> 5;       // 0..3
    const int g    = lane >> 2;
    const int q    = lane & 3;
    const int wm   = wid >> 1;       // 0..1
    const int wn   = wid & 1;        // 0..1
    const uint32_t sbase = (uint32_t)__cvta_generic_to_shared(dsm);

    // lane-only fragment addressing constants
    uint32_t AbaseL, BbaseL, acol[4], bcol[4];
    {
        int la = lane & 15, ca = lane >> 4;
        AbaseL = (wm * 64 + la) * 128;
#pragma unroll
        for (int j = 0; j < 4; ++j)
            acol[j] = ((j * 2 + ca) ^ (la & 7)) << 4;
        int lb = (lane & 7) + (lane >> 4) * 8, cb = (lane >> 3) & 1;
        BbaseL = ASTG + (wn * 64 + lb) * 128;
#pragma unroll
        for (int j = 0; j < 4; ++j)
            bcol[j] = ((j * 2 + cb) ^ (lb & 7)) << 4;
    }

    const int nx = N >> 7;           // tiles along N
    const int ntiles = (M >> 7) * nx;
    const int nkt = K / 64;          // 32

    for (int tile = blockIdx.x; tile < ntiles; tile += NSM_CTAS) {
        const int bm = (tile / nx) * 128;
        const int bn = (tile % nx) * 128;

        __syncthreads();   // all warps done reading prev tile's SMEM

        float acc[4][8][4];
#pragma unroll
        for (int mt = 0; mt < 4; ++mt)
#pragma unroll
            for (int nt = 0; nt < 8; ++nt)
#pragma unroll
                for (int i = 0; i < 4; ++i) acc[mt][nt][i] = 0.f;

        auto stage = [&](int s, int k0) {
            uint32_t ab = sbase + s * GSTG;
#pragma unroll
            for (int j = 0; j < 8; ++j) {
                int idx = j * 128 + tid;
                int row = idx >> 3, c = idx & 7;
                cp16(ab + row * 128 + (((c ^ (row & 7))) << 4),
                     A + (size_t)(bm + row) * K + k0 + c * 8);
            }
            uint32_t bb = ab + ASTG;
#pragma unroll
            for (int j = 0; j < 8; ++j) {
                int idx = j * 128 + tid;
                int row = idx >> 3, c = idx & 7;
                cp16(bb + row * 128 + (((c ^ (row & 7))) << 4),
                     B + (size_t)(bn + row) * K + k0 + c * 8);
            }
            cp_commit();
        };

        stage(0, 0);
        stage(1, 64);

        for (int kt = 0; kt < nkt; ++kt) {
            asm volatile("cp.async.wait_group 1;\n");
            __syncthreads();
            if (kt + 2 < nkt) stage((kt + 2) % 3, (kt + 2) * 64);
            else cp_commit();   // keep group accounting moving

            uint32_t aB = sbase + (kt % 3) * GSTG + AbaseL;
            uint32_t bB = sbase + (kt % 3) * GSTG + BbaseL;

#pragma unroll
            for (int j = 0; j < 4; ++j) {
                uint32_t af[4][4], bf[4][4];
#pragma unroll
                for (int np = 0; np < 4; ++np) ldm_x4(bf[np], bB + np * 2048 + bcol[j]);
#pragma unroll
                for (int mt = 0; mt < 4; ++mt) ldm_x4(af[mt], aB + mt * 2048 + acol[j]);
#pragma unroll
                for (int mt = 0; mt < 4; ++mt)
#pragma unroll
                    for (int np = 0; np < 4; ++np) {
                        mma_bf16(acc[mt][2 * np],     af[mt], &bf[np][0]);
                        mma_bf16(acc[mt][2 * np + 1], af[mt], &bf[np][2]);
                    }
            }
        }

        // Epilogue: Cb path folds softmax scale into Q columns (bn < DIM_)
        const float cs = (bn < DIM_) ? SL2E : 1.0f;
#pragma unroll
        for (int mt = 0; mt < 4; ++mt) {
            int r0 = bm + wm * 64 + mt * 16 + g;
#pragma unroll
            for (int nt = 0; nt < 8; ++nt) {
                int n0 = bn + wn * 64 + nt * 8 + 2 * q;
                if (Cb) {
                    *(uint32_t*)(Cb + (size_t)r0 * N + n0) =
                        pk_bf2(acc[mt][nt][0] * cs, acc[mt][nt][1] * cs);
                    *(uint32_t*)(Cb + (size_t)(r0 + 8) * N + n0) =
                        pk_bf2(acc[mt][nt][2] * cs, acc[mt][nt][3] * cs);
                } else {
                    float2 v0 = make_float2(acc[mt][nt][0], acc[mt][nt][1]);
                    float2 v1 = make_float2(acc[mt][nt][2], acc[mt][nt][3]);
                    if (res) {
                        float2 x0 = *(const float2*)(res + (size_t)r0 * N + n0);
                        float2 x1 = *(const float2*)(res + (size_t)(r0 + 8) * N + n0);
                        v0.x += x0.x; v0.y += x0.y; v1.x += x1.x; v1.y += x1.y;
                    }
                    *(float2*)(Cf + (size_t)r0 * N + n0) = v0;
                    *(float2*)(Cf + (size_t)(r0 + 8) * N + n0) = v1;
                }
            }
        }
    }
}

// ---------------------------------------------------------------------------
// Flash attention: q-tile=128 (8 warps x 16 rows), 64-key tiles.
// Scale pre-folded into Q; exp on MUFU; l via ones-mma. (R13 form)
// ---------------------------------------------------------------------------
#define ATT_SMEM 55296
#define KOFF 18432
#define VOFF 36864

__global__ void __launch_bounds__(256, 2) attn_bf16_kernel(
    const __nv_bfloat16* __restrict__ qkv, __nv_bfloat16* __restrict__ ao)
{
    extern __shared__ uint8_t asm_[];
    const uint32_t smbase = (uint32_t)__cvta_generic_to_shared(asm_);
    uint32_t* QP = (uint32_t*)asm_;

    const int tid  = threadIdx.x;
    const int lane = tid & 31;
    const int wid  = tid >> 5;
    const int g    = lane >> 2;
    const int q    = lane & 3;
    const int qt   = blockIdx.x;
    const int h    = blockIdx.y;
    const int b    = blockIdx.z;
    const int kvh  = h >> 2;
    const size_t tokbase = (size_t)b * LSEQ;
    const int q0 = qt * 128;

#pragma unroll
    for (int u = 0; u < 4; ++u) {
        int idx = u * 256 + tid;
        int row = idx >> 3, c = idx & 7;
        uint4 v = *(const uint4*)(qkv + (tokbase + q0 + row) * QKVD + h * HD + c * 8);
        ((uint4*)QP)[row * 9 + c] = v;
    }

    auto stageKV = [&](int s, int it) {
#pragma unroll
        for (int j = 0; j < 2; ++j) {
            int idx = j * 256 + tid;
            int row = idx >> 3, c = idx & 7;
            const __nv_bfloat16* base = qkv + (tokbase + it * 64 + row) * QKVD + DIM_ + kvh * HD;
            cp16(smbase + KOFF + s * 9216 + row * 144 + c * 16, base + c * 8);
            cp16(smbase + VOFF + s * 9216 + row * 144 + c * 16, base + 512 + c * 8);
        }
    };
    stageKV(0, 0);
    cp_commit();
    __syncthreads();

    uint32_t qa[4][4];
    {
        int rbase = (wid * 16 + g) * 36;
#pragma unroll
        for (int kt = 0; kt < 4; ++kt) {
            int c = kt * 8 + q;
            qa[kt][0] = QP[rbase + c];
            qa[kt][1] = QP[rbase + 8 * 36 + c];
            qa[kt][2] = QP[rbase + c + 4];
            qa[kt][3] = QP[rbase + 8 * 36 + c + 4];
        }
    }

    uint32_t koff[4], voff[4];
    {
        int lb = (lane & 7) + (lane >> 4) * 8, cb = (lane >> 3) & 1;
#pragma unroll
        for (int np = 0; np < 4; ++np)
            koff[np] = (np * 16 + lb) * 144 + cb * 16;
        int lv = lane & 15, hv = lane >> 4;
#pragma unroll
        for (int dp = 0; dp < 4; ++dp)
            voff[dp] = lv * 144 + dp * 32 + hv * 16;
    }

    float O[8][4];
#pragma unroll
    for (int nt = 0; nt < 8; ++nt)
#pragma unroll
        for (int i = 0; i < 4; ++i) O[nt][i] = 0.f;
    float lacc[4] = {0.f, 0.f, 0.f, 0.f};
    const uint32_t ONES2 = 0x3F803F80u;           // bf16 {1.0, 1.0}
    uint32_t onesb[2] = {ONES2, ONES2};

    for (int it = 0; it < LSEQ / 64; ++it) {
        asm volatile("cp.async.wait_group 0;\n");
        __syncthreads();
        if (it + 1 < LSEQ / 64) stageKV((it + 1) & 1, it + 1);
        cp_commit();

        const uint32_t kB = smbase + KOFF + (it & 1) * 9216;
        const uint32_t vB = smbase + VOFF + (it & 1) * 9216;

        // ---- S = Q @ K^T (scale already folded into Q) ----
        float S[8][4];
#pragma unroll
        for (int nt = 0; nt < 8; ++nt)
#pragma unroll
            for (int i = 0; i < 4; ++i) S[nt][i] = 0.f;

#pragma unroll
        for (int kt = 0; kt < 4; ++kt)
#pragma unroll
            for (int np = 0; np < 4; ++np) {
                uint32_t kf[4];
                ldm_x4(kf, kB + koff[np] + kt * 32);
                mma_bf16(S[2 * np],     qa[kt], &kf[0]);
                mma_bf16(S[2 * np + 1], qa[kt], &kf[2]);
            }

        // ---- per k16-group: V frags, exp on MUFU, l via ones-mma, PV mma ----
#pragma unroll
        for (int kt2 = 0; kt2 < 4; ++kt2) {
            uint32_t vf[4][4];
#pragma unroll
            for (int dp = 0; dp < 4; ++dp)
                ldm_x4t(vf[dp], vB + voff[dp] + kt2 * 2304);

            int nt0 = 2 * kt2, nt1 = 2 * kt2 + 1;
            float a0 = ex2m(S[nt0][0]);
            float a1 = ex2m(S[nt0][1]);
            float a2 = ex2m(S[nt0][2]);
            float a3 = ex2m(S[nt0][3]);
            float b0 = ex2m(S[nt1][0]);
            float b1 = ex2m(S[nt1][1]);
            float b2 = ex2m(S[nt1][2]);
            float b3 = ex2m(S[nt1][3]);
            uint32_t pa4[4];
            pa4[0] = pk_bf2(a0, a1);
            pa4[1] = pk_bf2(a2, a3);
            pa4[2] = pk_bf2(b0, b1);
            pa4[3] = pk_bf2(b2, b3);
            mma_bf16(lacc, pa4, onesb);        // row sums of P (all lanes)
#pragma unroll
            for (int dp = 0; dp < 4; ++dp) {
                mma_bf16(O[2 * dp],     pa4, &vf[dp][0]);
                mma_bf16(O[2 * dp + 1], pa4, &vf[dp][2]);
            }
        }
    }

    float inv0 = 1.0f / lacc[0], inv1 = 1.0f / lacc[2];
    int r0 = q0 + wid * 16 + g;
#pragma unroll
    for (int nt = 0; nt < 8; ++nt) {
        int col = h * HD + nt * 8 + 2 * q;
        *(uint32_t*)(ao + (tokbase + r0) * DIM_ + col)     = pk_bf2(O[nt][0] * inv0, O[nt][1] * inv0);
        *(uint32_t*)(ao + (tokbase + r0 + 8) * DIM_ + col) = pk_bf2(O[nt][2] * inv1, O[nt][3] * inv1);
    }
}

// ---------------------------------------------------------------------------
// LayerNorm: one CTA per row, in-place
// ---------------------------------------------------------------------------
__global__ void __launch_bounds__(256) ln_kernel(
    float* __restrict__ y, const float* __restrict__ gamma,
    const float* __restrict__ beta)
{
    __shared__ float sb[18];
    const int row = blockIdx.x;
    const int tid = threadIdx.x;
    float* p = y + (size_t)row * DIM_;

    float v[8];
    float s = 0.f, s2 = 0.f;
#pragma unroll
    for (int u = 0; u < 2; ++u) {
        float4 t = *(const float4*)(p + u * 1024 + tid * 4);
        v[u * 4 + 0] = t.x; v[u * 4 + 1] = t.y; v[u * 4 + 2] = t.z; v[u * 4 + 3] = t.w;
        s  += t.x + t.y + t.z + t.w;
        s2 += t.x * t.x + t.y * t.y + t.z * t.z + t.w * t.w;
    }
#pragma unroll
    for (int off = 16; off > 0; off >>= 1) {
        s  += __shfl_xor_sync(0xffffffffu, s,  off);
        s2 += __shfl_xor_sync(0xffffffffu, s2, off);
    }
    int w = tid >> 5;
    if ((tid & 31) == 0) { sb[w] = s; sb[8 + w] = s2; }
    __syncthreads();
    if (tid == 0) {
        float ts = 0.f, ts2 = 0.f;
#pragma unroll
        for (int i = 0; i < 8; ++i) { ts += sb[i]; ts2 += sb[8 + i]; }
        float mu  = ts * (1.0f / DIM_);
        float var = ts2 * (1.0f / DIM_) - mu * mu;
        sb[16] = mu;
        sb[17] = rsqrtf(var + 1e-5f);
    }
    __syncthreads();
    float mu = sb[16], rstd = sb[17];

#pragma unroll
    for (int u = 0; u < 2; ++u) {
        int col = u * 1024 + tid * 4;
        float4 gm = *(const float4*)(gamma + col);
        float4 bt = *(const float4*)(beta + col);
        float4 o;
        o.x = (v[u * 4 + 0] - mu) * rstd * gm.x + bt.x;
        o.y = (v[u * 4 + 1] - mu) * rstd * gm.y + bt.y;
        o.z = (v[u * 4 + 2] - mu) * rstd * gm.z + bt.z;
        o.w = (v[u * 4 + 3] - mu) * rstd * gm.w + bt.w;
        *(float4*)(p + col) = o;
    }
}

// ---------------------------------------------------------------------------
extern "C" void kernel_launch(void* const* d_in, const int* in_sizes, int n_in,
                              void* d_out, int out_size)
{
    const float* x     = (const float*)d_in[0];
    const float* w_qkv = (const float*)d_in[1];
    const float* w_out = (const float*)d_in[2];
    const float* gamma = (const float*)d_in[3];
    const float* beta  = (const float*)d_in[4];
    float* out = (float*)d_out;

    void *pxb, *pwq, *pwo, *pqk, *pao;
    cudaGetSymbolAddress(&pxb, g_xb);
    cudaGetSymbolAddress(&pwq, g_wqkvb);
    cudaGetSymbolAddress(&pwo, g_woutb);
    cudaGetSymbolAddress(&pqk, g_qkvb);
    cudaGetSymbolAddress(&pao, g_aob);
    __nv_bfloat16* xb    = (__nv_bfloat16*)pxb;
    __nv_bfloat16* wqkvb = (__nv_bfloat16*)pwq;
    __nv_bfloat16* woutb = (__nv_bfloat16*)pwo;
    __nv_bfloat16* qkvb  = (__nv_bfloat16*)pqk;
    __nv_bfloat16* aob   = (__nv_bfloat16*)pao;

    cudaFuncSetAttribute(gemm_bf16_kernel, cudaFuncAttributeMaxDynamicSharedMemorySize,
                         GEMM_SMEM);
    cudaFuncSetAttribute(attn_bf16_kernel, cudaFuncAttributeMaxDynamicSharedMemorySize,
                         ATT_SMEM);

    // 0) fused fp32 -> bf16 conversions (one launch)
    cvt3_kernel<<<CVT_TOTAL / (256 * 8), 256>>>(x, xb, w_qkv, wqkvb, w_out, woutb);

    // 1) QKV projection -> bf16 scratch (persistent; Q pre-scaled by SL2E)
    gemm_bf16_kernel<<<NSM_CTAS, 128, GEMM_SMEM>>>(xb, wqkvb, nullptr, nullptr, qkvb,
                                                   MTOK, QKVD, DIM_);

    // 2) GQA flash attention -> bf16 scratch
    dim3 g2(LSEQ / 128, HEADS, BSZ);
    attn_bf16_kernel<<<g2, 256, ATT_SMEM>>>(qkvb, aob);

    // 3) Output projection + residual -> d_out (persistent, fp32)
    gemm_bf16_kernel<<<NSM_CTAS, 128, GEMM_SMEM>>>(aob, woutb, x, out, nullptr,
                                                   MTOK, DIM_, DIM_);

    // 4) LayerNorm in-place
    ln_kernel<<<MTOK, 256>>>(out, gamma, beta);
}

// round 15
// speedup vs baseline: 1.1251x; 1.1251x over previous
#include <cuda_runtime.h>
#include <cuda_bf16.h>
#include <math.h>
#include <stdint.h>

// Problem constants
#define BSZ   2
#define LSEQ  2048
#define DIM_  2048
#define HEADS 32
#define HD    64
#define QKVD  3072
#define MTOK  4096

// Scratch (device globals; no allocation allowed)
__device__ __nv_bfloat16 g_xb   [(size_t)MTOK * DIM_];
__device__ __nv_bfloat16 g_wqkvb[(size_t)QKVD * DIM_];
__device__ __nv_bfloat16 g_woutb[(size_t)DIM_ * DIM_];
__device__ __nv_bfloat16 g_qkvb [(size_t)MTOK * QKVD];   // reused as GEMM2 out
__device__ __nv_bfloat16 g_aob  [(size_t)MTOK * DIM_];

#define SL2E 0.18033688011112042f   // 0.125 * log2(e), folded into Q at GEMM1

// ---------------------------------------------------------------------------
// Helpers
// ---------------------------------------------------------------------------
__device__ __forceinline__ uint32_t pk_bf2(float lo, float hi) {
    uint32_t r;
    asm("cvt.rn.bf16x2.f32 %0, %1, %2;" : "=r"(r) : "f"(hi), "f"(lo));
    return r;
}

__device__ __forceinline__ void mma_bf16(float c[4], const uint32_t a[4], const uint32_t b[2]) {
    asm volatile(
        "mma.sync.aligned.m16n8k16.row.col.f32.bf16.bf16.f32 "
        "{%0,%1,%2,%3}, {%4,%5,%6,%7}, {%8,%9}, {%0,%1,%2,%3};\n"
        : "+f"(c[0]), "+f"(c[1]), "+f"(c[2]), "+f"(c[3])
        : "r"(a[0]), "r"(a[1]), "r"(a[2]), "r"(a[3]), "r"(b[0]), "r"(b[1]));
}

__device__ __forceinline__ void ldm_x4(uint32_t r[4], uint32_t addr) {
    asm volatile("ldmatrix.sync.aligned.m8n8.x4.shared.b16 {%0,%1,%2,%3}, [%4];\n"
                 : "=r"(r[0]), "=r"(r[1]), "=r"(r[2]), "=r"(r[3]) : "r"(addr));
}
__device__ __forceinline__ void ldm_x4t(uint32_t r[4], uint32_t addr) {
    asm volatile("ldmatrix.sync.aligned.m8n8.x4.trans.shared.b16 {%0,%1,%2,%3}, [%4];\n"
                 : "=r"(r[0]), "=r"(r[1]), "=r"(r[2]), "=r"(r[3]) : "r"(addr));
}

__device__ __forceinline__ void cp16(uint32_t dst, const void* src) {
    asm volatile("cp.async.cg.shared.global [%0], [%1], 16;\n" :: "r"(dst), "l"(src));
}
__device__ __forceinline__ void cp_commit() {
    asm volatile("cp.async.commit_group;\n");
}

// exp2 on the MUFU pipe (parallel to FMA + tensor pipes)
__device__ __forceinline__ float ex2m(float x) {
    float r;
    asm("ex2.approx.f32 %0, %1;" : "=f"(r) : "f"(x));
    return r;
}

// ---------------------------------------------------------------------------
// fused fp32 -> bf16 conversion of x, w_qkv, w_out (one launch)
// ---------------------------------------------------------------------------
#define CVT_N1 (MTOK * DIM_)
#define CVT_N2 (QKVD * DIM_)
#define CVT_N3 (DIM_ * DIM_)
#define CVT_TOTAL (CVT_N1 + CVT_N2 + CVT_N3)

__global__ void __launch_bounds__(256) cvt3_kernel(
    const float* __restrict__ s1, __nv_bfloat16* __restrict__ d1,
    const float* __restrict__ s2, __nv_bfloat16* __restrict__ d2,
    const float* __restrict__ s3, __nv_bfloat16* __restrict__ d3)
{
    int i = (blockIdx.x * 256 + threadIdx.x) * 8;
    const float* s;
    __nv_bfloat16* d;
    if (i < CVT_N1)                  { s = s1 + i;                 d = d1 + i; }
    else if (i < CVT_N1 + CVT_N2)    { s = s2 + (i - CVT_N1);      d = d2 + (i - CVT_N1); }
    else if (i < CVT_TOTAL)          { s = s3 + (i - CVT_N1 - CVT_N2); d = d3 + (i - CVT_N1 - CVT_N2); }
    else return;
    float4 a = *(const float4*)s;
    float4 b = *(const float4*)(s + 4);
    uint4 o;
    o.x = pk_bf2(a.x, a.y);
    o.y = pk_bf2(a.z, a.w);
    o.z = pk_bf2(b.x, b.y);
    o.w = pk_bf2(b.z, b.w);
    *(uint4*)d = o;
}

// ---------------------------------------------------------------------------
// bf16 NT GEMM: BM=128, BN=128, BK=64, 3-stage cp.async.
// 128 threads = 4 warps of 64x64, 2 CTAs/SM. bf16 output only (light tail).
// Columns n < qscale_n are scaled by SL2E in the epilogue (Q pre-scale).
// ---------------------------------------------------------------------------
#define ASTG 16384
#define GSTG 32768
#define GEMM_SMEM (3 * GSTG)   // 98304

__global__ void __launch_bounds__(128, 2) gemm_bf16_kernel(
    const __nv_bfloat16* __restrict__ A, const __nv_bfloat16* __restrict__ B,
    __nv_bfloat16* __restrict__ Cb, int M, int N, int K, int qscale_n)
{
    extern __shared__ uint8_t dsm[];
    const int tid  = threadIdx.x;
    const int lane = tid & 31;
    const int wid  = tid >> 5;       // 0..3
    const int g    = lane >> 2;
    const int q    = lane & 3;
    const int wm   = wid >> 1;       // 0..1
    const int wn   = wid & 1;        // 0..1
    const int bm   = blockIdx.y * 128;
    const int bn   = blockIdx.x * 128;
    const uint32_t sbase = (uint32_t)__cvta_generic_to_shared(dsm);

    float acc[4][8][4];
#pragma unroll
    for (int mt = 0; mt < 4; ++mt)
#pragma unroll
        for (int nt = 0; nt < 8; ++nt)
#pragma unroll
            for (int i = 0; i < 4; ++i) acc[mt][nt][i] = 0.f;

    // compact fragment addressing: XOR sel depends only on lane
    uint32_t Abase, Bbase, acol[4], bcol[4];
    {
        int la = lane & 15, ca = lane >> 4;
        Abase = (wm * 64 + la) * 128;
#pragma unroll
        for (int j = 0; j < 4; ++j)
            acol[j] = ((j * 2 + ca) ^ (la & 7)) << 4;
        int lb = (lane & 7) + (lane >> 4) * 8, cb = (lane >> 3) & 1;
        Bbase = ASTG + (wn * 64 + lb) * 128;
#pragma unroll
        for (int j = 0; j < 4; ++j)
            bcol[j] = ((j * 2 + cb) ^ (lb & 7)) << 4;
    }

    auto stage = [&](int s, int k0) {
        uint32_t ab = sbase + s * GSTG;
#pragma unroll
        for (int j = 0; j < 8; ++j) {
            int idx = j * 128 + tid;
            int row = idx >> 3, c = idx & 7;
            cp16(ab + row * 128 + (((c ^ (row & 7))) << 4),
                 A + (size_t)(bm + row) * K + k0 + c * 8);
        }
        uint32_t bb = ab + ASTG;
#pragma unroll
        for (int j = 0; j < 8; ++j) {
            int idx = j * 128 + tid;
            int row = idx >> 3, c = idx & 7;
            cp16(bb + row * 128 + (((c ^ (row & 7))) << 4),
                 B + (size_t)(bn + row) * K + k0 + c * 8);
        }
        cp_commit();
    };

    const int nkt = K / 64;          // 32
    stage(0, 0);
    stage(1, 64);

    for (int kt = 0; kt < nkt; ++kt) {
        asm volatile("cp.async.wait_group 1;\n");
        __syncthreads();
        if (kt + 2 < nkt) stage((kt + 2) % 3, (kt + 2) * 64);
        else cp_commit();   // keep group accounting moving

        uint32_t aB = sbase + (kt % 3) * GSTG + Abase;
        uint32_t bB = sbase + (kt % 3) * GSTG + Bbase;

#pragma unroll
        for (int j = 0; j < 4; ++j) {
            uint32_t af[4][4], bf[4][4];
#pragma unroll
            for (int np = 0; np < 4; ++np) ldm_x4(bf[np], bB + np * 2048 + bcol[j]);
#pragma unroll
            for (int mt = 0; mt < 4; ++mt) ldm_x4(af[mt], aB + mt * 2048 + acol[j]);
#pragma unroll
            for (int mt = 0; mt < 4; ++mt)
#pragma unroll
                for (int np = 0; np < 4; ++np) {
                    mma_bf16(acc[mt][2 * np],     af[mt], &bf[np][0]);
                    mma_bf16(acc[mt][2 * np + 1], af[mt], &bf[np][2]);
                }
        }
    }

    // Epilogue: bf16 pack; Q columns (n < qscale_n) scaled by SL2E
    const float cs = (bn < qscale_n) ? SL2E : 1.0f;
#pragma unroll
    for (int mt = 0; mt < 4; ++mt) {
        int r0 = bm + wm * 64 + mt * 16 + g;
#pragma unroll
        for (int nt = 0; nt < 8; ++nt) {
            int n0 = bn + wn * 64 + nt * 8 + 2 * q;
            *(uint32_t*)(Cb + (size_t)r0 * N + n0) =
                pk_bf2(acc[mt][nt][0] * cs, acc[mt][nt][1] * cs);
            *(uint32_t*)(Cb + (size_t)(r0 + 8) * N + n0) =
                pk_bf2(acc[mt][nt][2] * cs, acc[mt][nt][3] * cs);
        }
    }
}

// ---------------------------------------------------------------------------
// Flash attention: q-tile=128 (8 warps x 16 rows), 64-key tiles.
// Scale pre-folded into Q; exp on MUFU; l via ones-mma. (R13 form)
// ---------------------------------------------------------------------------
#define ATT_SMEM 55296
#define KOFF 18432
#define VOFF 36864

__global__ void __launch_bounds__(256, 2) attn_bf16_kernel(
    const __nv_bfloat16* __restrict__ qkv, __nv_bfloat16* __restrict__ ao)
{
    extern __shared__ uint8_t asm_[];
    const uint32_t smbase = (uint32_t)__cvta_generic_to_shared(asm_);
    uint32_t* QP = (uint32_t*)asm_;

    const int tid  = threadIdx.x;
    const int lane = tid & 31;
    const int wid  = tid >> 5;
    const int g    = lane >> 2;
    const int q    = lane & 3;
    const int qt   = blockIdx.x;
    const int h    = blockIdx.y;
    const int b    = blockIdx.z;
    const int kvh  = h >> 2;
    const size_t tokbase = (size_t)b * LSEQ;
    const int q0 = qt * 128;

#pragma unroll
    for (int u = 0; u < 4; ++u) {
        int idx = u * 256 + tid;
        int row = idx >> 3, c = idx & 7;
        uint4 v = *(const uint4*)(qkv + (tokbase + q0 + row) * QKVD + h * HD + c * 8);
        ((uint4*)QP)[row * 9 + c] = v;
    }

    auto stageKV = [&](int s, int it) {
#pragma unroll
        for (int j = 0; j < 2; ++j) {
            int idx = j * 256 + tid;
            int row = idx >> 3, c = idx & 7;
            const __nv_bfloat16* base = qkv + (tokbase + it * 64 + row) * QKVD + DIM_ + kvh * HD;
            cp16(smbase + KOFF + s * 9216 + row * 144 + c * 16, base + c * 8);
            cp16(smbase + VOFF + s * 9216 + row * 144 + c * 16, base + 512 + c * 8);
        }
    };
    stageKV(0, 0);
    cp_commit();
    __syncthreads();

    uint32_t qa[4][4];
    {
        int rbase = (wid * 16 + g) * 36;
#pragma unroll
        for (int kt = 0; kt < 4; ++kt) {
            int c = kt * 8 + q;
            qa[kt][0] = QP[rbase + c];
            qa[kt][1] = QP[rbase + 8 * 36 + c];
            qa[kt][2] = QP[rbase + c + 4];
            qa[kt][3] = QP[rbase + 8 * 36 + c + 4];
        }
    }

    uint32_t koff[4], voff[4];
    {
        int lb = (lane & 7) + (lane >> 4) * 8, cb = (lane >> 3) & 1;
#pragma unroll
        for (int np = 0; np < 4; ++np)
            koff[np] = (np * 16 + lb) * 144 + cb * 16;
        int lv = lane & 15, hv = lane >> 4;
#pragma unroll
        for (int dp = 0; dp < 4; ++dp)
            voff[dp] = lv * 144 + dp * 32 + hv * 16;
    }

    float O[8][4];
#pragma unroll
    for (int nt = 0; nt < 8; ++nt)
#pragma unroll
        for (int i = 0; i < 4; ++i) O[nt][i] = 0.f;
    float lacc[4] = {0.f, 0.f, 0.f, 0.f};
    const uint32_t ONES2 = 0x3F803F80u;           // bf16 {1.0, 1.0}
    uint32_t onesb[2] = {ONES2, ONES2};

    for (int it = 0; it < LSEQ / 64; ++it) {
        asm volatile("cp.async.wait_group 0;\n");
        __syncthreads();
        if (it + 1 < LSEQ / 64) stageKV((it + 1) & 1, it + 1);
        cp_commit();

        const uint32_t kB = smbase + KOFF + (it & 1) * 9216;
        const uint32_t vB = smbase + VOFF + (it & 1) * 9216;

        // ---- S = Q @ K^T (scale already folded into Q) ----
        float S[8][4];
#pragma unroll
        for (int nt = 0; nt < 8; ++nt)
#pragma unroll
            for (int i = 0; i < 4; ++i) S[nt][i] = 0.f;

#pragma unroll
        for (int kt = 0; kt < 4; ++kt)
#pragma unroll
            for (int np = 0; np < 4; ++np) {
                uint32_t kf[4];
                ldm_x4(kf, kB + koff[np] + kt * 32);
                mma_bf16(S[2 * np],     qa[kt], &kf[0]);
                mma_bf16(S[2 * np + 1], qa[kt], &kf[2]);
            }

        // ---- per k16-group: V frags, exp on MUFU, l via ones-mma, PV mma ----
#pragma unroll
        for (int kt2 = 0; kt2 < 4; ++kt2) {
            uint32_t vf[4][4];
#pragma unroll
            for (int dp = 0; dp < 4; ++dp)
                ldm_x4t(vf[dp], vB + voff[dp] + kt2 * 2304);

            int nt0 = 2 * kt2, nt1 = 2 * kt2 + 1;
            float a0 = ex2m(S[nt0][0]);
            float a1 = ex2m(S[nt0][1]);
            float a2 = ex2m(S[nt0][2]);
            float a3 = ex2m(S[nt0][3]);
            float b0 = ex2m(S[nt1][0]);
            float b1 = ex2m(S[nt1][1]);
            float b2 = ex2m(S[nt1][2]);
            float b3 = ex2m(S[nt1][3]);
            uint32_t pa4[4];
            pa4[0] = pk_bf2(a0, a1);
            pa4[1] = pk_bf2(a2, a3);
            pa4[2] = pk_bf2(b0, b1);
            pa4[3] = pk_bf2(b2, b3);
            mma_bf16(lacc, pa4, onesb);        // row sums of P (all lanes)
#pragma unroll
            for (int dp = 0; dp < 4; ++dp) {
                mma_bf16(O[2 * dp],     pa4, &vf[dp][0]);
                mma_bf16(O[2 * dp + 1], pa4, &vf[dp][2]);
            }
        }
    }

    float inv0 = 1.0f / lacc[0], inv1 = 1.0f / lacc[2];
    int r0 = q0 + wid * 16 + g;
#pragma unroll
    for (int nt = 0; nt < 8; ++nt) {
        int col = h * HD + nt * 8 + 2 * q;
        *(uint32_t*)(ao + (tokbase + r0) * DIM_ + col)     = pk_bf2(O[nt][0] * inv0, O[nt][1] * inv0);
        *(uint32_t*)(ao + (tokbase + r0 + 8) * DIM_ + col) = pk_bf2(O[nt][2] * inv1, O[nt][3] * inv1);
    }
}

// ---------------------------------------------------------------------------
// Fused residual + LayerNorm: y = LN(x + ob), ob in bf16, out fp32.
// One CTA per row.
// ---------------------------------------------------------------------------
__global__ void __launch_bounds__(256) ln_res_kernel(
    const float* __restrict__ x, const __nv_bfloat16* __restrict__ ob,
    const float* __restrict__ gamma, const float* __restrict__ beta,
    float* __restrict__ out)
{
    __shared__ float sb[18];
    const int row = blockIdx.x;
    const int tid = threadIdx.x;
    const float* px = x + (size_t)row * DIM_;
    const __nv_bfloat16* po = ob + (size_t)row * DIM_;
    float* py = out + (size_t)row * DIM_;

    float v[8];
    float s = 0.f, s2 = 0.f;
#pragma unroll
    for (int u = 0; u < 2; ++u) {
        int col = u * 1024 + tid * 4;
        float4 t = *(const float4*)(px + col);
        uint2 ob2 = *(const uint2*)(po + col);
        __nv_bfloat162 o01 = *(__nv_bfloat162*)&ob2.x;
        __nv_bfloat162 o23 = *(__nv_bfloat162*)&ob2.y;
        float y0 = t.x + __bfloat162float(o01.x);
        float y1 = t.y + __bfloat162float(o01.y);
        float y2 = t.z + __bfloat162float(o23.x);
        float y3 = t.w + __bfloat162float(o23.y);
        v[u * 4 + 0] = y0; v[u * 4 + 1] = y1; v[u * 4 + 2] = y2; v[u * 4 + 3] = y3;
        s  += y0 + y1 + y2 + y3;
        s2 += y0 * y0 + y1 * y1 + y2 * y2 + y3 * y3;
    }
#pragma unroll
    for (int off = 16; off > 0; off >>= 1) {
        s  += __shfl_xor_sync(0xffffffffu, s,  off);
        s2 += __shfl_xor_sync(0xffffffffu, s2, off);
    }
    int w = tid >> 5;
    if ((tid & 31) == 0) { sb[w] = s; sb[8 + w] = s2; }
    __syncthreads();
    if (tid == 0) {
        float ts = 0.f, ts2 = 0.f;
#pragma unroll
        for (int i = 0; i < 8; ++i) { ts += sb[i]; ts2 += sb[8 + i]; }
        float mu  = ts * (1.0f / DIM_);
        float var = ts2 * (1.0f / DIM_) - mu * mu;
        sb[16] = mu;
        sb[17] = rsqrtf(var + 1e-5f);
    }
    __syncthreads();
    float mu = sb[16], rstd = sb[17];

#pragma unroll
    for (int u = 0; u < 2; ++u) {
        int col = u * 1024 + tid * 4;
        float4 gm = *(const float4*)(gamma + col);
        float4 bt = *(const float4*)(beta + col);
        float4 o;
        o.x = (v[u * 4 + 0] - mu) * rstd * gm.x + bt.x;
        o.y = (v[u * 4 + 1] - mu) * rstd * gm.y + bt.y;
        o.z = (v[u * 4 + 2] - mu) * rstd * gm.z + bt.z;
        o.w = (v[u * 4 + 3] - mu) * rstd * gm.w + bt.w;
        *(float4*)(py + col) = o;
    }
}

// ---------------------------------------------------------------------------
extern "C" void kernel_launch(void* const* d_in, const int* in_sizes, int n_in,
                              void* d_out, int out_size)
{
    const float* x     = (const float*)d_in[0];
    const float* w_qkv = (const float*)d_in[1];
    const float* w_out = (const float*)d_in[2];
    const float* gamma = (const float*)d_in[3];
    const float* beta  = (const float*)d_in[4];
    float* out = (float*)d_out;

    void *pxb, *pwq, *pwo, *pqk, *pao;
    cudaGetSymbolAddress(&pxb, g_xb);
    cudaGetSymbolAddress(&pwq, g_wqkvb);
    cudaGetSymbolAddress(&pwo, g_woutb);
    cudaGetSymbolAddress(&pqk, g_qkvb);
    cudaGetSymbolAddress(&pao, g_aob);
    __nv_bfloat16* xb    = (__nv_bfloat16*)pxb;
    __nv_bfloat16* wqkvb = (__nv_bfloat16*)pwq;
    __nv_bfloat16* woutb = (__nv_bfloat16*)pwo;
    __nv_bfloat16* qkvb  = (__nv_bfloat16*)pqk;
    __nv_bfloat16* aob   = (__nv_bfloat16*)pao;
    __nv_bfloat16* ob    = qkvb;   // reuse retired qkv scratch for GEMM2 output

    cudaFuncSetAttribute(gemm_bf16_kernel, cudaFuncAttributeMaxDynamicSharedMemorySize,
                         GEMM_SMEM);
    cudaFuncSetAttribute(attn_bf16_kernel, cudaFuncAttributeMaxDynamicSharedMemorySize,
                         ATT_SMEM);

    // 0) fused fp32 -> bf16 conversions (one launch)
    cvt3_kernel<<<CVT_TOTAL / (256 * 8), 256>>>(x, xb, w_qkv, wqkvb, w_out, woutb);

    // 1) QKV projection -> bf16 scratch (Q columns pre-scaled by SL2E)
    dim3 g1(QKVD / 128, MTOK / 128);
    gemm_bf16_kernel<<<g1, 128, GEMM_SMEM>>>(xb, wqkvb, qkvb, MTOK, QKVD, DIM_, DIM_);

    // 2) GQA flash attention -> bf16 scratch
    dim3 g2(LSEQ / 128, HEADS, BSZ);
    attn_bf16_kernel<<<g2, 256, ATT_SMEM>>>(qkvb, aob);

    // 3) Output projection -> bf16 scratch (no residual; light epilogue)
    dim3 g3(DIM_ / 128, MTOK / 128);
    gemm_bf16_kernel<<<g3, 128, GEMM_SMEM>>>(aob, woutb, ob, MTOK, DIM_, DIM_, 0);

    // 4) Fused residual + LayerNorm -> d_out
    ln_res_kernel<<<MTOK, 256>>>(x, ob, gamma, beta, out);
}